// round 3
// baseline (speedup 1.0000x reference)
#include <cuda_runtime.h>

#define Hh 160
#define Ww 160
#define Bn 4
#define HW (Hh*Ww)

// ---------------- scratch (device globals; no allocation allowed) ----------------
__device__ float g_h1[(size_t)Bn*128*HW];     // conv1 out
__device__ float g_h2[(size_t)Bn*128*HW];     // conv2 out
__device__ float g_off[(size_t)Bn*18*HW];     // offset conv out
__device__ float g_hrT[(size_t)Bn*HW*64];     // hr in NHWC
__device__ float g_samp[(size_t)Bn*576*HW];   // bilinear samples, [b][c*9+k][h][w]
__device__ float g_w1T[1152*128];
__device__ float g_w2T[1152*128];
__device__ float g_woT[1152*32];              // padded 18 -> 32
__device__ float g_wdT[576*64];

// ---------------- packed f32x2 helpers ----------------
__device__ __forceinline__ unsigned long long ffma2(unsigned long long a,
                                                    unsigned long long b,
                                                    unsigned long long c)
{
    unsigned long long d;
    asm("fma.rn.f32x2 %0, %1, %2, %3;" : "=l"(d) : "l"(a), "l"(b), "l"(c));
    return d;
}
__device__ __forceinline__ unsigned long long pack2(float lo, float hi)
{
    unsigned long long d;
    asm("mov.b64 %0, {%1, %2};" : "=l"(d) : "f"(lo), "f"(hi));
    return d;
}
__device__ __forceinline__ float2 unpack2(unsigned long long v)
{
    float lo, hi;
    asm("mov.b64 {%0, %1}, %2;" : "=f"(lo), "=f"(hi) : "l"(v));
    return make_float2(lo, hi);
}

// ---------------- weight reformat: [O][CINK] -> [CINK][O_pad] (zero padded) ----------------
__global__ void transpose_w(const float* __restrict__ w, float* __restrict__ wT,
                            int COUT, int COUT_PAD, int CINK)
{
    int i = blockIdx.x*blockDim.x + threadIdx.x;
    if (i >= CINK*COUT_PAD) return;
    int o = i % COUT_PAD;
    int j = i / COUT_PAD;
    wT[i] = (o < COUT) ? w[(size_t)o*CINK + j] : 0.f;
}

// ---------------- hr NCHW -> NHWC ----------------
__global__ void hr_transpose(const float* __restrict__ hr, float* __restrict__ hrT)
{
    int idx = blockIdx.x*blockDim.x + threadIdx.x;
    if (idx >= Bn*64*HW) return;
    int x = idx % Ww;
    int y = (idx / Ww) % Hh;
    int c = (idx / HW) % 64;
    int b = idx / (64*HW);
    hrT[(((size_t)b*HW) + (size_t)y*Ww + x)*64 + c] = hr[idx];
}

// ---------------- tiled direct conv / 1x1 GEMM, FFMA2 inner loop ----------------
// Block tile: OC_TILE = OCG*4 output channels  x  128 pixels (32 wide x 4 rows).
// Thread: 4 contiguous oc (as 2 packed pairs) x (4 contiguous x) x (2 rows) = 32 acc (16 u64).
// Threads = OCG*16:  tx = t&7 (x group), tyy = (t>>3)&1 (row pair), tg = t>>4 (oc group).
// Weights pre-transposed: wT[(cin*KS*KS + k)*COUT_PAD + oc]  -> LDS.128 = 2 packed oc pairs.
// Inputs staged DUPLICATED in smem so LDS.128 yields (i,i) packed operands directly.
template<int OCG, int KS, bool RELU>
__global__ void __launch_bounds__(OCG*16)
conv_tiled(const float* __restrict__ in0,
           const float* __restrict__ in1,     // second half of channel concat (or null)
           const float* __restrict__ wT,
           const float* __restrict__ bias,    // or null
           float* __restrict__ out,
           int CIN, int CIN0, int COUT, int COUT_PAD)
{
    constexpr int OC_TILE = OCG*4;
    constexpr int CK = 4;
    constexpr int KK = KS*KS;
    constexpr int SR = (KS==3) ? 6 : 4;
    constexpr int IW = (KS==3) ? 34 : 32;           // logical halo width
    constexpr int SW2 = (KS==3) ? 76 : 68;          // duplicated row stride (floats), 16B-aligned, bank-staggered
    constexpr int NT = OCG*16;

    __shared__ __align__(16) float s_in[CK][SR][SW2];   // duplicated: [..][2*x+d]
    __shared__ __align__(16) float s_w[CK][KK][OC_TILE];

    const int t   = threadIdx.x;
    const int tx  = t & 7;
    const int tyy = (t >> 3) & 1;
    const int tg  = t >> 4;

    const int noct = COUT_PAD / OC_TILE;
    const int oct  = blockIdx.z % noct;
    const int b    = blockIdx.z / noct;
    const int xb   = blockIdx.x * 32;
    const int yb   = blockIdx.y * 4;
    const int oc0  = oct * OC_TILE;
    const int x0   = tx * 4;
    const int myoc = oc0 + tg*4;

    unsigned long long bini[2];
    #pragma unroll
    for (int op = 0; op < 2; op++) {
        float blo = (bias != nullptr && (myoc+2*op  ) < COUT) ? bias[myoc+2*op  ] : 0.f;
        float bhi = (bias != nullptr && (myoc+2*op+1) < COUT) ? bias[myoc+2*op+1] : 0.f;
        bini[op] = pack2(blo, bhi);
    }

    unsigned long long acc[2][4][2];
    #pragma unroll
    for (int r = 0; r < 2; r++)
        #pragma unroll
        for (int j = 0; j < 4; j++)
            #pragma unroll
            for (int op = 0; op < 2; op++)
                acc[r][j][op] = bini[op];

    const int CIN1 = CIN - CIN0;

    for (int ci0 = 0; ci0 < CIN; ci0 += CK) {
        // stage input tile (zero-padded halo for KS==3), duplicated {v,v}
        for (int e = t; e < CK*SR*IW; e += NT) {
            int ci  = e / (SR*IW);
            int rem = e - ci*(SR*IW);
            int r   = rem / IW;
            int c   = rem - r*IW;
            int gy  = yb + r - (KS==3 ? 1 : 0);
            int gx  = xb + c - (KS==3 ? 1 : 0);
            float v = 0.f;
            if (gy >= 0 && gy < Hh && gx >= 0 && gx < Ww) {
                int cin = ci0 + ci;
                const float* p = (cin < CIN0)
                    ? (in0 + ((size_t)b*CIN0 + cin)*HW)
                    : (in1 + ((size_t)b*CIN1 + (cin - CIN0))*HW);
                v = p[gy*Ww + gx];
            }
            *(float2*)&s_in[ci][r][2*c] = make_float2(v, v);
        }
        // stage weights (coalesced: oc contiguous)
        for (int e = t; e < CK*KK*OC_TILE; e += NT) {
            int oc  = e % OC_TILE;
            int rem = e / OC_TILE;
            int k   = rem % KK;
            int ci  = rem / KK;
            s_w[ci][k][oc] = wT[((size_t)(ci0+ci)*KK + k)*COUT_PAD + oc0 + oc];
        }
        __syncthreads();

        #pragma unroll
        for (int ci = 0; ci < CK; ci++) {
            if (KS == 3) {
                #pragma unroll
                for (int ky = 0; ky < 3; ky++) {
                    const float* r0p = &s_in[ci][tyy*2 + ky    ][2*x0];
                    const float* r1p = &s_in[ci][tyy*2 + 1 + ky][2*x0];
                    ulonglong2 a0 = ((const ulonglong2*)r0p)[0];
                    ulonglong2 a1 = ((const ulonglong2*)r0p)[1];
                    ulonglong2 a2 = ((const ulonglong2*)r0p)[2];
                    ulonglong2 c0 = ((const ulonglong2*)r1p)[0];
                    ulonglong2 c1 = ((const ulonglong2*)r1p)[1];
                    ulonglong2 c2 = ((const ulonglong2*)r1p)[2];
                    unsigned long long i0[6] = {a0.x, a0.y, a1.x, a1.y, a2.x, a2.y};
                    unsigned long long i1[6] = {c0.x, c0.y, c1.x, c1.y, c2.x, c2.y};
                    #pragma unroll
                    for (int kx = 0; kx < 3; kx++) {
                        ulonglong2 wv = *(const ulonglong2*)&s_w[ci][ky*3+kx][tg*4];
                        #pragma unroll
                        for (int j = 0; j < 4; j++) {
                            acc[0][j][0] = ffma2(i0[j+kx], wv.x, acc[0][j][0]);
                            acc[0][j][1] = ffma2(i0[j+kx], wv.y, acc[0][j][1]);
                            acc[1][j][0] = ffma2(i1[j+kx], wv.x, acc[1][j][0]);
                            acc[1][j][1] = ffma2(i1[j+kx], wv.y, acc[1][j][1]);
                        }
                    }
                }
            } else {
                const float* r0p = &s_in[ci][tyy*2    ][2*x0];
                const float* r1p = &s_in[ci][tyy*2 + 1][2*x0];
                ulonglong2 a0 = ((const ulonglong2*)r0p)[0];
                ulonglong2 a1 = ((const ulonglong2*)r0p)[1];
                ulonglong2 c0 = ((const ulonglong2*)r1p)[0];
                ulonglong2 c1 = ((const ulonglong2*)r1p)[1];
                unsigned long long i0[4] = {a0.x, a0.y, a1.x, a1.y};
                unsigned long long i1[4] = {c0.x, c0.y, c1.x, c1.y};
                ulonglong2 wv = *(const ulonglong2*)&s_w[ci][0][tg*4];
                #pragma unroll
                for (int j = 0; j < 4; j++) {
                    acc[0][j][0] = ffma2(i0[j], wv.x, acc[0][j][0]);
                    acc[0][j][1] = ffma2(i0[j], wv.y, acc[0][j][1]);
                    acc[1][j][0] = ffma2(i1[j], wv.x, acc[1][j][0]);
                    acc[1][j][1] = ffma2(i1[j], wv.y, acc[1][j][1]);
                }
            }
        }
        __syncthreads();
    }

    #pragma unroll
    for (int o = 0; o < 4; o++) {
        int oc = myoc + o;
        if (oc < COUT) {
            #pragma unroll
            for (int r = 0; r < 2; r++) {
                int y = yb + tyy*2 + r;
                float4 v;
                float2 p0 = unpack2(acc[r][0][o>>1]);
                float2 p1 = unpack2(acc[r][1][o>>1]);
                float2 p2 = unpack2(acc[r][2][o>>1]);
                float2 p3 = unpack2(acc[r][3][o>>1]);
                v.x = (o&1) ? p0.y : p0.x;
                v.y = (o&1) ? p1.y : p1.x;
                v.z = (o&1) ? p2.y : p2.x;
                v.w = (o&1) ? p3.y : p3.x;
                if (RELU) {
                    v.x = fmaxf(v.x, 0.f); v.y = fmaxf(v.y, 0.f);
                    v.z = fmaxf(v.z, 0.f); v.w = fmaxf(v.w, 0.f);
                }
                *(float4*)&out[((size_t)b*COUT + oc)*HW + (size_t)y*Ww + xb + x0] = v;
            }
        }
    }
}

// ---------------- bilinear sampling (hr in NHWC; 16 channels/thread via LDG.128) ----------------
__global__ void deform_sample(const float* __restrict__ hrT,
                              const float* __restrict__ off,
                              float* __restrict__ samp)
{
    int idx = blockIdx.x*blockDim.x + threadIdx.x;
    if (idx >= Bn*9*4*HW) return;
    int x  = idx % Ww;
    int y  = (idx / Ww) % Hh;
    int cg = (idx / HW) & 3;
    int k  = (idx / (HW*4)) % 9;
    int b  = idx / (HW*36);
    int ky = k/3 - 1;
    int kx = k%3 - 1;

    size_t opix = ((size_t)b*18)*HW + (size_t)y*Ww + x;
    float dy = off[opix + (size_t)(2*k  )*HW];
    float dx = off[opix + (size_t)(2*k+1)*HW];

    float py = (float)(y + ky) + dy;
    float px = (float)(x + kx) + dx;
    float y0f = floorf(py), x0f = floorf(px);
    float wy = py - y0f, wx = px - x0f;
    int yi = (int)y0f, xi = (int)x0f;

    bool vy0 = (yi   >= 0) && (yi   <= Hh-1);
    bool vy1 = (yi+1 >= 0) && (yi+1 <= Hh-1);
    bool vx0 = (xi   >= 0) && (xi   <= Ww-1);
    bool vx1 = (xi+1 >= 0) && (xi+1 <= Ww-1);
    int yc0 = min(max(yi,   0), Hh-1);
    int yc1 = min(max(yi+1, 0), Hh-1);
    int xc0 = min(max(xi,   0), Ww-1);
    int xc1 = min(max(xi+1, 0), Ww-1);

    float w00 = (1.f-wy)*(1.f-wx) * ((vy0 && vx0) ? 1.f : 0.f);
    float w01 = (1.f-wy)*wx       * ((vy0 && vx1) ? 1.f : 0.f);
    float w10 = wy*(1.f-wx)       * ((vy1 && vx0) ? 1.f : 0.f);
    float w11 = wy*wx             * ((vy1 && vx1) ? 1.f : 0.f);

    const float* base = hrT + (size_t)b*HW*64 + cg*16;
    const float4* p00 = (const float4*)(base + ((size_t)yc0*Ww + xc0)*64);
    const float4* p01 = (const float4*)(base + ((size_t)yc0*Ww + xc1)*64);
    const float4* p10 = (const float4*)(base + ((size_t)yc1*Ww + xc0)*64);
    const float4* p11 = (const float4*)(base + ((size_t)yc1*Ww + xc1)*64);

    float o16[16];
    #pragma unroll
    for (int q = 0; q < 4; q++) {
        float4 a = p00[q], bq = p01[q], c4 = p10[q], d = p11[q];
        o16[q*4+0] = w00*a.x + w01*bq.x + w10*c4.x + w11*d.x;
        o16[q*4+1] = w00*a.y + w01*bq.y + w10*c4.y + w11*d.y;
        o16[q*4+2] = w00*a.z + w01*bq.z + w10*c4.z + w11*d.z;
        o16[q*4+3] = w00*a.w + w01*bq.w + w10*c4.w + w11*d.w;
    }

    size_t sb = ((size_t)b*576 + k)*HW + (size_t)y*Ww + x;
    #pragma unroll
    for (int c = 0; c < 16; c++)
        samp[sb + (size_t)(cg*16 + c)*9*HW] = o16[c];
}

// ---------------- launch ----------------
extern "C" void kernel_launch(void* const* d_in, const int* in_sizes, int n_in,
                              void* d_out, int out_size)
{
    (void)in_sizes; (void)n_in; (void)out_size;
    const float* lr = (const float*)d_in[0];
    const float* hr = (const float*)d_in[1];
    const float* w1 = (const float*)d_in[2];
    const float* b1 = (const float*)d_in[3];
    const float* w2 = (const float*)d_in[4];
    const float* b2 = (const float*)d_in[5];
    const float* wo = (const float*)d_in[6];
    const float* wd = (const float*)d_in[7];
    float* out = (float*)d_out;

    float *ph1, *ph2, *poff, *phrT, *psamp, *pw1T, *pw2T, *pwoT, *pwdT;
    cudaGetSymbolAddress((void**)&ph1,  g_h1);
    cudaGetSymbolAddress((void**)&ph2,  g_h2);
    cudaGetSymbolAddress((void**)&poff, g_off);
    cudaGetSymbolAddress((void**)&phrT, g_hrT);
    cudaGetSymbolAddress((void**)&psamp,g_samp);
    cudaGetSymbolAddress((void**)&pw1T, g_w1T);
    cudaGetSymbolAddress((void**)&pw2T, g_w2T);
    cudaGetSymbolAddress((void**)&pwoT, g_woT);
    cudaGetSymbolAddress((void**)&pwdT, g_wdT);

    // weight reformats + hr NHWC (cheap)
    transpose_w<<<(1152*128 + 255)/256, 256>>>(w1, pw1T, 128, 128, 1152);
    transpose_w<<<(1152*128 + 255)/256, 256>>>(w2, pw2T, 128, 128, 1152);
    transpose_w<<<(1152*32  + 255)/256, 256>>>(wo, pwoT, 18,  32,  1152);
    transpose_w<<<(576*64   + 255)/256, 256>>>(wd, pwdT, 64,  64,  576);
    hr_transpose<<<(Bn*64*HW + 255)/256, 256>>>(hr, phrT);

    // conv1: concat(lr,hr) -> 128, relu
    conv_tiled<16,3,true ><<<dim3(5,40,8), 256>>>(lr,  hr,      pw1T, b1,      ph1, 128, 64,  128, 128);
    // conv2: 128 -> 128, relu
    conv_tiled<16,3,true ><<<dim3(5,40,8), 256>>>(ph1, nullptr, pw2T, b2,      ph2, 128, 128, 128, 128);
    // offset conv: 128 -> 18 (padded 32)
    conv_tiled<8, 3,false><<<dim3(5,40,4), 128>>>(ph2, nullptr, pwoT, nullptr, poff,128, 128, 18,  32);
    // bilinear sampling
    deform_sample<<<(Bn*9*4*HW + 255)/256, 256>>>(phrT, poff, psamp);
    // deform contraction as 1x1 conv: 576 -> 64
    conv_tiled<16,1,false><<<dim3(5,40,4), 256>>>(psamp, nullptr, pwdT, nullptr, out, 576, 576, 64, 64);
}

// round 5
// speedup vs baseline: 2.5036x; 2.5036x over previous
#include <cuda_runtime.h>
#include <cuda_fp16.h>
#include <cstdint>

#define Hh 160
#define Ww 160
#define Bn 4
#define HW (Hh*Ww)

// ---------------- scratch (device globals; no allocation allowed) ----------------
__device__ float g_xcat[(size_t)Bn*HW*128];   // concat(lr,hr) NHWC
__device__ float g_h1[(size_t)Bn*HW*128];     // conv1 out NHWC
__device__ float g_h2[(size_t)Bn*HW*128];     // conv2 out NHWC
__device__ float g_off[(size_t)Bn*HW*32];     // offset conv out NHWC (18 used, pad 32)
__device__ float g_hrT[(size_t)Bn*HW*64];     // hr NHWC
__device__ float g_samp[(size_t)Bn*HW*576];   // samples: [pix][tap*64+cin]
// weights pre-split fp16 hi/lo, pre-swizzled smem image: [kc][oc][128 bytes]
__device__ __align__(16) __half g_BT1[36*128*64];
__device__ __align__(16) __half g_BT2[36*128*64];
__device__ __align__(16) __half g_BTo[36*32*64];
__device__ __align__(16) __half g_BTd[18*64*64];

// ---------------- helpers ----------------
__device__ __forceinline__ uint32_t smem_u32(const void* p) {
    uint32_t a;
    asm("{ .reg .u64 t; cvta.to.shared.u64 t, %1; cvt.u32.u64 %0, t; }" : "=r"(a) : "l"(p));
    return a;
}
__device__ __forceinline__ void ldm4(uint32_t* r, uint32_t addr) {
    asm volatile("ldmatrix.sync.aligned.m8n8.x4.shared.b16 {%0,%1,%2,%3}, [%4];"
                 : "=r"(r[0]), "=r"(r[1]), "=r"(r[2]), "=r"(r[3]) : "r"(addr));
}
__device__ __forceinline__ void mma16816(float* c, const uint32_t* a, const uint32_t* b) {
    asm volatile("mma.sync.aligned.m16n8k16.row.col.f32.f16.f16.f32 "
                 "{%0,%1,%2,%3}, {%4,%5,%6,%7}, {%8,%9}, {%0,%1,%2,%3};"
                 : "+f"(c[0]), "+f"(c[1]), "+f"(c[2]), "+f"(c[3])
                 : "r"(a[0]), "r"(a[1]), "r"(a[2]), "r"(a[3]), "r"(b[0]), "r"(b[1]));
}
__device__ __forceinline__ void st128(uint32_t a, uint4 v) {
    asm volatile("st.shared.v4.b32 [%0], {%1,%2,%3,%4};"
                 :: "r"(a), "r"(v.x), "r"(v.y), "r"(v.z), "r"(v.w) : "memory");
}
__device__ __forceinline__ uint32_t packh2(__half a, __half b) {
    __half2 h = __halves2half2(a, b);
    return *reinterpret_cast<uint32_t*>(&h);
}
// split 8 floats into hi/lo fp16 chunks (16B each)
__device__ __forceinline__ void split8(float4 u, float4 v, uint4& hi, uint4& lo) {
    float f[8] = {u.x,u.y,u.z,u.w, v.x,v.y,v.z,v.w};
    __half h[8], l[8];
    #pragma unroll
    for (int i = 0; i < 8; i++) {
        h[i] = __float2half_rn(f[i]);
        l[i] = __float2half_rn(f[i] - __half2float(h[i]));
    }
    hi = make_uint4(packh2(h[0],h[1]), packh2(h[2],h[3]), packh2(h[4],h[5]), packh2(h[6],h[7]));
    lo = make_uint4(packh2(l[0],l[1]), packh2(l[2],l[3]), packh2(l[4],l[5]), packh2(l[6],l[7]));
}

// ---------------- implicit-GEMM conv on mma.sync fp16 (3-term split, f32 accum) ----------------
// Block tile: M=128 px (4 rows x 32 x) x N oc. 8 warps = WM x WN. K chunked by 32.
// smem rows: 128B = [hi k0..31 | lo k0..31], 16B-chunk swizzle: ch ^= (row & 7).
template<int N, int WN, bool GATHER, bool NCHW_OUT, bool RELU, int NCH, int CIN>
__global__ void __launch_bounds__(256)
mma_conv(const float* __restrict__ in, const __half* __restrict__ BT,
         const float* __restrict__ bias, float* __restrict__ out,
         int CS, int OUT_CS)
{
    constexpr int WM = 8 / WN;
    constexpr int MT = 128 / WM;
    constexpr int NT = N / WN;
    constexpr int MF = MT / 16;
    constexpr int NF = NT / 8;
    constexpr int ABUF = 128 * 128;
    constexpr int BBUF = N * 128;
    constexpr int BV = N / 32;            // uint4 per thread for B staging

    extern __shared__ __align__(16) char dsm[];
    const uint32_t smb = (smem_u32(dsm) + 127u) & ~127u;
    const uint32_t Ab0 = smb, Ab1 = smb + ABUF;
    const uint32_t Bb0 = smb + 2*ABUF, Bb1 = smb + 2*ABUF + BBUF;

    const int t = threadIdx.x;
    const int w = t >> 5, lane = t & 31;
    const int wm = w % WM, wn = w / WM;
    const int xb = blockIdx.x * 32, yb = blockIdx.y * 4, b = blockIdx.z;

    float acc[MF][NF][4];
    #pragma unroll
    for (int i = 0; i < MF; i++)
        #pragma unroll
        for (int j = 0; j < NF; j++)
            #pragma unroll
            for (int r = 0; r < 4; r++) acc[i][j][r] = 0.f;

    const int px = t >> 1, half = t & 1;
    const int prow = px >> 5, pcol = px & 31;

    float4 av[4];
    uint4  bv[BV];

    auto load_a = [&](int kc) {
        const float* src;
        bool ok = true;
        if (GATHER) {
            constexpr int CPT = CIN / 32;                  // chunks per tap
            const int tap = kc / CPT, cinb = (kc % CPT) * 32;
            const int gy = yb + prow + tap/3 - 1;
            const int gx = xb + pcol + tap%3 - 1;
            ok = (gy >= 0 && gy < Hh && gx >= 0 && gx < Ww);
            src = in + ((size_t)b*HW + (size_t)gy*Ww + gx)*CS + cinb + half*16;
        } else {
            const int pix = (yb + prow)*Ww + xb + pcol;
            src = in + ((size_t)b*HW + pix)*CS + kc*32 + half*16;
        }
        if (ok) {
            #pragma unroll
            for (int i = 0; i < 4; i++) av[i] = ((const float4*)src)[i];
        } else {
            #pragma unroll
            for (int i = 0; i < 4; i++) av[i] = make_float4(0.f,0.f,0.f,0.f);
        }
    };
    auto load_b = [&](int kc) {
        const uint4* src = (const uint4*)(BT + (size_t)kc*N*64);
        #pragma unroll
        for (int i = 0; i < BV; i++) bv[i] = src[t + i*256];
    };
    auto sts_ab = [&](uint32_t Ab, uint32_t Bb) {
        const uint32_t rowb = Ab + px*128;
        const uint32_t sw = px & 7;
        #pragma unroll
        for (int i = 0; i < 2; i++) {
            uint4 hi, lo;
            split8(av[2*i], av[2*i+1], hi, lo);
            const int ch = half*2 + i;
            st128(rowb + (uint32_t)((ch ^ sw) << 4), hi);
            st128(rowb + (uint32_t)(((ch+4) ^ sw) << 4), lo);
        }
        #pragma unroll
        for (int i = 0; i < BV; i++) st128(Bb + t*16 + i*4096, bv[i]);
    };
    auto compute = [&](uint32_t Ab, uint32_t Bb) {
        #pragma unroll
        for (int ks = 0; ks < 2; ks++) {
            uint32_t ah[MF][4], al[MF][4];
            #pragma unroll
            for (int mf = 0; mf < MF; mf++) {
                const int row = wm*MT + mf*16 + (lane & 15);
                const int chh = ks*2 + (lane >> 4);
                const uint32_t rb = Ab + row*128;
                ldm4(ah[mf], rb + (uint32_t)((chh ^ (row&7)) << 4));
                ldm4(al[mf], rb + (uint32_t)(((chh+4) ^ (row&7)) << 4));
            }
            #pragma unroll
            for (int nf2 = 0; nf2 < NF/2; nf2++) {
                uint32_t bh[4], bl[4];
                const int oc  = wn*NT + nf2*16 + (lane & 7) + ((lane >> 4) << 3);
                const int chb = ks*2 + ((lane >> 3) & 1);
                const uint32_t rb = Bb + oc*128;
                ldm4(bh, rb + (uint32_t)((chb ^ (oc&7)) << 4));
                ldm4(bl, rb + (uint32_t)(((chb+4) ^ (oc&7)) << 4));
                #pragma unroll
                for (int mf = 0; mf < MF; mf++) {
                    mma16816(acc[mf][2*nf2  ], ah[mf], bh+0);
                    mma16816(acc[mf][2*nf2  ], ah[mf], bl+0);
                    mma16816(acc[mf][2*nf2  ], al[mf], bh+0);
                    mma16816(acc[mf][2*nf2+1], ah[mf], bh+2);
                    mma16816(acc[mf][2*nf2+1], ah[mf], bl+2);
                    mma16816(acc[mf][2*nf2+1], al[mf], bh+2);
                }
            }
        }
    };

    load_a(0); load_b(0);
    sts_ab(Ab0, Bb0);
    __syncthreads();

    for (int kc = 0; kc < NCH; kc++) {
        if (kc + 1 < NCH) { load_a(kc+1); load_b(kc+1); }
        compute((kc & 1) ? Ab1 : Ab0, (kc & 1) ? Bb1 : Bb0);
        if (kc + 1 < NCH) {
            sts_ab(((kc+1) & 1) ? Ab1 : Ab0, ((kc+1) & 1) ? Bb1 : Bb0);
            __syncthreads();
        }
    }

    // ---- epilogue ----
    const int lrow = lane >> 2, lcol = (lane & 3) * 2;
    #pragma unroll
    for (int mf = 0; mf < MF; mf++) {
        #pragma unroll
        for (int nf = 0; nf < NF; nf++) {
            const int oc = wn*NT + nf*8 + lcol;
            float bx = 0.f, by = 0.f;
            if (bias != nullptr) { bx = __ldg(bias + oc); by = __ldg(bias + oc + 1); }
            #pragma unroll
            for (int rp = 0; rp < 2; rp++) {
                const int m = wm*MT + mf*16 + lrow + rp*8;
                const int y = yb + (m >> 5), x = xb + (m & 31);
                float c0 = acc[mf][nf][rp*2] + bx;
                float c1 = acc[mf][nf][rp*2+1] + by;
                if (RELU) { c0 = fmaxf(c0, 0.f); c1 = fmaxf(c1, 0.f); }
                if (!NCHW_OUT) {
                    *(float2*)(out + ((size_t)b*HW + (size_t)y*Ww + x)*OUT_CS + oc)
                        = make_float2(c0, c1);
                } else {
                    const size_t p = (size_t)y*Ww + x;
                    out[((size_t)b*N + oc  )*HW + p] = c0;
                    out[((size_t)b*N + oc+1)*HW + p] = c1;
                }
            }
        }
    }
}

// ---------------- NCHW -> NHWC tiled transpose ----------------
__global__ void to_nhwc(const float* __restrict__ src, float* __restrict__ dst,
                        int C, int OCS, int cofs)
{
    __shared__ float tl[32][33];
    const int p0 = blockIdx.x*32, c0 = blockIdx.y*32, b = blockIdx.z;
    const int lx = threadIdx.x & 31, ly = threadIdx.x >> 5;
    #pragma unroll
    for (int i = 0; i < 32; i += 8)
        tl[ly+i][lx] = src[((size_t)b*C + c0 + ly + i)*HW + p0 + lx];
    __syncthreads();
    #pragma unroll
    for (int i = 0; i < 32; i += 8)
        dst[((size_t)b*HW + p0 + ly + i)*OCS + cofs + c0 + lx] = tl[lx][ly+i];
}

// ---------------- weight reformat: split fp16 hi/lo + pre-swizzle smem image ----------------
__global__ void reformat_w_split(const float* __restrict__ w, __half* __restrict__ BT,
                                 int COUT, int NPAD, int CIN, int TOT)
{
    int i = blockIdx.x*blockDim.x + threadIdx.x;
    if (i >= TOT) return;
    int j  = i & 31;
    int oc = (i >> 5) % NPAD;
    int kc = i / (32 * NPAD);
    int kidx = kc*32 + j;
    int tap = kidx / CIN, cin = kidx % CIN;
    float v = (oc < COUT) ? w[((size_t)oc*CIN + cin)*9 + tap] : 0.f;
    __half h = __float2half_rn(v);
    __half l = __float2half_rn(v - __half2float(h));
    int sw = oc & 7;
    size_t rowb = ((size_t)kc*NPAD + oc) * 64;
    int ch = j >> 3, pos = j & 7;
    BT[rowb + (size_t)(((ch    ) ^ sw) << 3) + pos] = h;
    BT[rowb + (size_t)(((ch + 4) ^ sw) << 3) + pos] = l;
}

// ---------------- bilinear sampling (hr NHWC; writes samp[pix][tap*64+cin]) ----------------
__global__ void deform_sample(const float* __restrict__ hrT,
                              const float* __restrict__ off,
                              float* __restrict__ samp)
{
    int idx = blockIdx.x*blockDim.x + threadIdx.x;
    if (idx >= Bn*9*4*HW) return;
    int x  = idx % Ww;
    int y  = (idx / Ww) % Hh;
    int cg = (idx / HW) & 3;
    int k  = (idx / (HW*4)) % 9;
    int b  = idx / (HW*36);
    int ky = k/3 - 1;
    int kx = k%3 - 1;

    size_t pix = (size_t)b*HW + (size_t)y*Ww + x;
    float dy = off[pix*32 + 2*k    ];
    float dx = off[pix*32 + 2*k + 1];

    float py  = (float)(y + ky) + dy;
    float pxx = (float)(x + kx) + dx;
    float y0f = floorf(py), x0f = floorf(pxx);
    float wy = py - y0f, wx = pxx - x0f;
    int yi = (int)y0f, xi = (int)x0f;

    bool vy0 = (yi   >= 0) && (yi   <= Hh-1);
    bool vy1 = (yi+1 >= 0) && (yi+1 <= Hh-1);
    bool vx0 = (xi   >= 0) && (xi   <= Ww-1);
    bool vx1 = (xi+1 >= 0) && (xi+1 <= Ww-1);
    int yc0 = min(max(yi,   0), Hh-1);
    int yc1 = min(max(yi+1, 0), Hh-1);
    int xc0 = min(max(xi,   0), Ww-1);
    int xc1 = min(max(xi+1, 0), Ww-1);

    float w00 = (1.f-wy)*(1.f-wx) * ((vy0 && vx0) ? 1.f : 0.f);
    float w01 = (1.f-wy)*wx       * ((vy0 && vx1) ? 1.f : 0.f);
    float w10 = wy*(1.f-wx)       * ((vy1 && vx0) ? 1.f : 0.f);
    float w11 = wy*wx             * ((vy1 && vx1) ? 1.f : 0.f);

    const float* base = hrT + (size_t)b*HW*64 + cg*16;
    const float4* p00 = (const float4*)(base + ((size_t)yc0*Ww + xc0)*64);
    const float4* p01 = (const float4*)(base + ((size_t)yc0*Ww + xc1)*64);
    const float4* p10 = (const float4*)(base + ((size_t)yc1*Ww + xc0)*64);
    const float4* p11 = (const float4*)(base + ((size_t)yc1*Ww + xc1)*64);

    float4* dst = (float4*)(samp + pix*576 + k*64 + cg*16);
    #pragma unroll
    for (int q = 0; q < 4; q++) {
        float4 a = p00[q], bq = p01[q], c4 = p10[q], d = p11[q];
        float4 o;
        o.x = w00*a.x + w01*bq.x + w10*c4.x + w11*d.x;
        o.y = w00*a.y + w01*bq.y + w10*c4.y + w11*d.y;
        o.z = w00*a.z + w01*bq.z + w10*c4.z + w11*d.z;
        o.w = w00*a.w + w01*bq.w + w10*c4.w + w11*d.w;
        dst[q] = o;
    }
}

// ---------------- launch ----------------
extern "C" void kernel_launch(void* const* d_in, const int* in_sizes, int n_in,
                              void* d_out, int out_size)
{
    (void)in_sizes; (void)n_in; (void)out_size;
    const float* lr = (const float*)d_in[0];
    const float* hr = (const float*)d_in[1];
    const float* w1 = (const float*)d_in[2];
    const float* b1 = (const float*)d_in[3];
    const float* w2 = (const float*)d_in[4];
    const float* b2 = (const float*)d_in[5];
    const float* wo = (const float*)d_in[6];
    const float* wd = (const float*)d_in[7];
    float* out = (float*)d_out;

    float *pxcat, *ph1, *ph2, *poff, *phrT, *psamp;
    __half *pBT1, *pBT2, *pBTo, *pBTd;
    cudaGetSymbolAddress((void**)&pxcat, g_xcat);
    cudaGetSymbolAddress((void**)&ph1,  g_h1);
    cudaGetSymbolAddress((void**)&ph2,  g_h2);
    cudaGetSymbolAddress((void**)&poff, g_off);
    cudaGetSymbolAddress((void**)&phrT, g_hrT);
    cudaGetSymbolAddress((void**)&psamp,g_samp);
    cudaGetSymbolAddress((void**)&pBT1, g_BT1);
    cudaGetSymbolAddress((void**)&pBT2, g_BT2);
    cudaGetSymbolAddress((void**)&pBTo, g_BTo);
    cudaGetSymbolAddress((void**)&pBTd, g_BTd);

    const int SZ128 = 2*16384 + 2*128*128;   // 65536
    const int SZ32  = 2*16384 + 2*32*128;    // 40960
    const int SZ64  = 2*16384 + 2*64*128;    // 49152
    cudaFuncSetAttribute(mma_conv<128,2,true ,false,true ,36,128>,
                         cudaFuncAttributeMaxDynamicSharedMemorySize, SZ128);
    cudaFuncSetAttribute(mma_conv<32 ,1,true ,false,false,36,128>,
                         cudaFuncAttributeMaxDynamicSharedMemorySize, SZ32);
    cudaFuncSetAttribute(mma_conv<64 ,2,false,true ,false,18,64>,
                         cudaFuncAttributeMaxDynamicSharedMemorySize, SZ64);

    // layout prep
    to_nhwc<<<dim3(800,2,Bn), 256>>>(lr, pxcat, 64, 128, 0);
    to_nhwc<<<dim3(800,2,Bn), 256>>>(hr, pxcat, 64, 128, 64);
    to_nhwc<<<dim3(800,2,Bn), 256>>>(hr, phrT,  64, 64,  0);
    reformat_w_split<<<(36*128*32+255)/256, 256>>>(w1, pBT1, 128, 128, 128, 36*128*32);
    reformat_w_split<<<(36*128*32+255)/256, 256>>>(w2, pBT2, 128, 128, 128, 36*128*32);
    reformat_w_split<<<(36*32*32 +255)/256, 256>>>(wo, pBTo, 18,  32,  128, 36*32*32);
    reformat_w_split<<<(18*64*32 +255)/256, 256>>>(wd, pBTd, 64,  64,  64,  18*64*32);

    // conv1: xcat(128) -> 128, relu
    mma_conv<128,2,true ,false,true ,36,128><<<dim3(5,40,Bn), 256, SZ128>>>(pxcat, pBT1, b1, ph1, 128, 128);
    // conv2: 128 -> 128, relu
    mma_conv<128,2,true ,false,true ,36,128><<<dim3(5,40,Bn), 256, SZ128>>>(ph1,   pBT2, b2, ph2, 128, 128);
    // offset conv: 128 -> 18 (pad 32)
    mma_conv<32 ,1,true ,false,false,36,128><<<dim3(5,40,Bn), 256, SZ32 >>>(ph2,   pBTo, nullptr, poff, 128, 32);
    // bilinear sampling
    deform_sample<<<(Bn*9*4*HW + 255)/256, 256>>>(phrT, poff, psamp);
    // deform contraction: K=576 -> 64, NCHW output
    mma_conv<64 ,2,false,true ,false,18,64 ><<<dim3(5,40,Bn), 256, SZ64 >>>(psamp, pBTd, nullptr, out, 576, 0);
}

// round 6
// speedup vs baseline: 3.0134x; 1.2036x over previous
#include <cuda_runtime.h>
#include <cuda_fp16.h>
#include <cstdint>

#define Hh 160
#define Ww 160
#define Bn 4
#define HW (Hh*Ww)

// ---------------- scratch (device globals; no allocation allowed) ----------------
__device__ float g_lrT[(size_t)Bn*HW*64];     // lr NHWC
__device__ float g_hrT[(size_t)Bn*HW*64];     // hr NHWC
__device__ float g_h1[(size_t)Bn*HW*128];     // conv1 out NHWC
__device__ float g_h2[(size_t)Bn*HW*128];     // conv2 out NHWC
__device__ float g_off[(size_t)Bn*HW*32];     // offset conv out NHWC (18 used, pad 32)
// weights pre-split fp16 hi/lo, pre-swizzled smem image: [kc][oc][128 bytes]
__device__ __align__(16) __half g_BT1[36*128*64];
__device__ __align__(16) __half g_BT2[36*128*64];
__device__ __align__(16) __half g_BTo[36*32*64];
__device__ __align__(16) __half g_BTd[18*64*64];

// ---------------- helpers ----------------
__device__ __forceinline__ uint32_t smem_u32(const void* p) {
    uint32_t a;
    asm("{ .reg .u64 t; cvta.to.shared.u64 t, %1; cvt.u32.u64 %0, t; }" : "=r"(a) : "l"(p));
    return a;
}
__device__ __forceinline__ void ldm4(uint32_t* r, uint32_t addr) {
    asm volatile("ldmatrix.sync.aligned.m8n8.x4.shared.b16 {%0,%1,%2,%3}, [%4];"
                 : "=r"(r[0]), "=r"(r[1]), "=r"(r[2]), "=r"(r[3]) : "r"(addr));
}
__device__ __forceinline__ void mma16816(float* c, const uint32_t* a, const uint32_t* b) {
    asm volatile("mma.sync.aligned.m16n8k16.row.col.f32.f16.f16.f32 "
                 "{%0,%1,%2,%3}, {%4,%5,%6,%7}, {%8,%9}, {%0,%1,%2,%3};"
                 : "+f"(c[0]), "+f"(c[1]), "+f"(c[2]), "+f"(c[3])
                 : "r"(a[0]), "r"(a[1]), "r"(a[2]), "r"(a[3]), "r"(b[0]), "r"(b[1]));
}
__device__ __forceinline__ void st128(uint32_t a, uint4 v) {
    asm volatile("st.shared.v4.b32 [%0], {%1,%2,%3,%4};"
                 :: "r"(a), "r"(v.x), "r"(v.y), "r"(v.z), "r"(v.w) : "memory");
}
__device__ __forceinline__ uint32_t packh2(__half a, __half b) {
    __half2 h = __halves2half2(a, b);
    return *reinterpret_cast<uint32_t*>(&h);
}
// split 8 floats into hi/lo fp16 chunks (16B each)
__device__ __forceinline__ void split8(float4 u, float4 v, uint4& hi, uint4& lo) {
    float f[8] = {u.x,u.y,u.z,u.w, v.x,v.y,v.z,v.w};
    __half h[8], l[8];
    #pragma unroll
    for (int i = 0; i < 8; i++) {
        h[i] = __float2half_rn(f[i]);
        l[i] = __float2half_rn(f[i] - __half2float(h[i]));
    }
    hi = make_uint4(packh2(h[0],h[1]), packh2(h[2],h[3]), packh2(h[4],h[5]), packh2(h[6],h[7]));
    lo = make_uint4(packh2(l[0],l[1]), packh2(l[2],l[3]), packh2(l[4],l[5]), packh2(l[6],l[7]));
}

// ---------------- implicit-GEMM conv on mma.sync fp16 (3-term split, f32 accum) ----------------
// MODE 0: 3x3 conv, NHWC in (optionally concat in0|in1), NHWC out.
// MODE 2: fused deformable sampling + 1x1 contraction over K=tap*64+cin, NCHW out.
// Block tile: M=128 px (4 rows x 32 x) x N oc. 8 warps = WM x WN. K chunked by 32.
// smem rows: 128B = [hi k0..31 | lo k0..31], 16B-chunk swizzle: ch ^= (row & 7).
template<int N, int WN, int MODE, bool RELU, int NCH, int CPT>
__global__ void __launch_bounds__(256)
mma_conv(const float* __restrict__ in0, const float* __restrict__ in1,
         const float* __restrict__ offp, const __half* __restrict__ BT,
         const float* __restrict__ bias, float* __restrict__ out,
         int CS0, int CS1, int CIN0, int OUT_CS)
{
    constexpr int WM = 8 / WN;
    constexpr int MT = 128 / WM;
    constexpr int NT = N / WN;
    constexpr int MF = MT / 16;
    constexpr int NF = NT / 8;
    constexpr int ABUF = 128 * 128;
    constexpr int BBUF = N * 128;
    constexpr int BV = (N >= 32) ? N / 32 : 1;

    extern __shared__ __align__(16) char dsm[];
    const uint32_t smb = (smem_u32(dsm) + 127u) & ~127u;
    const uint32_t Ab0 = smb, Ab1 = smb + ABUF;
    const uint32_t Bb0 = smb + 2*ABUF, Bb1 = smb + 2*ABUF + BBUF;

    const int t = threadIdx.x;
    const int w = t >> 5, lane = t & 31;
    const int wm = w % WM, wn = w / WM;
    const int xb = blockIdx.x * 32, yb = blockIdx.y * 4, b = blockIdx.z;

    float acc[MF][NF][4];
    #pragma unroll
    for (int i = 0; i < MF; i++)
        #pragma unroll
        for (int j = 0; j < NF; j++)
            #pragma unroll
            for (int r = 0; r < 4; r++) acc[i][j][r] = 0.f;

    const int px = t >> 1, half = t & 1;
    const int prow = px >> 5, pcol = px & 31;

    float4 av[4];
    uint4  bv[BV];

    auto load_a = [&](int kc) {
        if (MODE == 0) {
            const int tap = kc / CPT;
            const int cb  = (kc % CPT) * 32 + half * 16;
            const int gy = yb + prow + tap/3 - 1;
            const int gx = xb + pcol + tap%3 - 1;
            if (gy >= 0 && gy < Hh && gx >= 0 && gx < Ww) {
                const size_t pix = (size_t)b*HW + (size_t)gy*Ww + gx;
                const float* src = (cb < CIN0) ? in0 + pix*CS0 + cb
                                               : in1 + pix*CS1 + (cb - CIN0);
                #pragma unroll
                for (int i = 0; i < 4; i++) av[i] = ((const float4*)src)[i];
            } else {
                #pragma unroll
                for (int i = 0; i < 4; i++) av[i] = make_float4(0.f,0.f,0.f,0.f);
            }
        } else {
            // fused deformable bilinear gather: tap = kc/2, channels (kc&1)*32 + half*16
            const int tap = kc >> 1;
            const int cb  = ((kc & 1) << 5) + half * 16;
            const int y = yb + prow, x = xb + pcol;
            const size_t pix = (size_t)b*HW + (size_t)y*Ww + x;
            const float dy = offp[pix*32 + 2*tap];
            const float dx = offp[pix*32 + 2*tap + 1];
            const float py  = (float)(y + tap/3 - 1) + dy;
            const float pxx = (float)(x + tap%3 - 1) + dx;
            const float y0f = floorf(py), x0f = floorf(pxx);
            const float wy = py - y0f, wx = pxx - x0f;
            const int yi = (int)y0f, xi = (int)x0f;
            const bool vy0 = (yi   >= 0) && (yi   <= Hh-1);
            const bool vy1 = (yi+1 >= 0) && (yi+1 <= Hh-1);
            const bool vx0 = (xi   >= 0) && (xi   <= Ww-1);
            const bool vx1 = (xi+1 >= 0) && (xi+1 <= Ww-1);
            const int yc0 = min(max(yi,   0), Hh-1);
            const int yc1 = min(max(yi+1, 0), Hh-1);
            const int xc0 = min(max(xi,   0), Ww-1);
            const int xc1 = min(max(xi+1, 0), Ww-1);
            const float w00 = (1.f-wy)*(1.f-wx) * ((vy0 && vx0) ? 1.f : 0.f);
            const float w01 = (1.f-wy)*wx       * ((vy0 && vx1) ? 1.f : 0.f);
            const float w10 = wy*(1.f-wx)       * ((vy1 && vx0) ? 1.f : 0.f);
            const float w11 = wy*wx             * ((vy1 && vx1) ? 1.f : 0.f);
            const float* base = in0 + (size_t)b*HW*64 + cb;
            const float4* p00 = (const float4*)(base + ((size_t)yc0*Ww + xc0)*64);
            const float4* p01 = (const float4*)(base + ((size_t)yc0*Ww + xc1)*64);
            const float4* p10 = (const float4*)(base + ((size_t)yc1*Ww + xc0)*64);
            const float4* p11 = (const float4*)(base + ((size_t)yc1*Ww + xc1)*64);
            #pragma unroll
            for (int i = 0; i < 4; i++) {
                float4 a = p00[i], bq = p01[i], c4 = p10[i], d = p11[i];
                av[i].x = w00*a.x + w01*bq.x + w10*c4.x + w11*d.x;
                av[i].y = w00*a.y + w01*bq.y + w10*c4.y + w11*d.y;
                av[i].z = w00*a.z + w01*bq.z + w10*c4.z + w11*d.z;
                av[i].w = w00*a.w + w01*bq.w + w10*c4.w + w11*d.w;
            }
        }
    };
    auto load_b = [&](int kc) {
        const uint4* src = (const uint4*)(BT + (size_t)kc*N*64);
        #pragma unroll
        for (int i = 0; i < BV; i++) {
            const int e = t + i*256;
            if (N >= 32 || e < N*8) bv[i] = src[e];
        }
    };
    auto sts_ab = [&](uint32_t Ab, uint32_t Bb) {
        const uint32_t rowb = Ab + px*128;
        const uint32_t sw = px & 7;
        #pragma unroll
        for (int i = 0; i < 2; i++) {
            uint4 hi, lo;
            split8(av[2*i], av[2*i+1], hi, lo);
            const int ch = half*2 + i;
            st128(rowb + (uint32_t)((ch ^ sw) << 4), hi);
            st128(rowb + (uint32_t)(((ch+4) ^ sw) << 4), lo);
        }
        #pragma unroll
        for (int i = 0; i < BV; i++) {
            const int e = t + i*256;
            if (N >= 32 || e < N*8) st128(Bb + e*16, bv[i]);
        }
    };
    auto compute = [&](uint32_t Ab, uint32_t Bb) {
        #pragma unroll
        for (int ks = 0; ks < 2; ks++) {
            uint32_t ah[MF][4], al[MF][4];
            #pragma unroll
            for (int mf = 0; mf < MF; mf++) {
                const int row = wm*MT + mf*16 + (lane & 15);
                const int chh = ks*2 + (lane >> 4);
                const uint32_t rb = Ab + row*128;
                ldm4(ah[mf], rb + (uint32_t)((chh ^ (row&7)) << 4));
                ldm4(al[mf], rb + (uint32_t)(((chh+4) ^ (row&7)) << 4));
            }
            #pragma unroll
            for (int nf2 = 0; nf2 < NF/2; nf2++) {
                uint32_t bh[4], bl[4];
                const int oc  = wn*NT + nf2*16 + (lane & 7) + ((lane >> 4) << 3);
                const int chb = ks*2 + ((lane >> 3) & 1);
                const uint32_t rb = Bb + oc*128;
                ldm4(bh, rb + (uint32_t)((chb ^ (oc&7)) << 4));
                ldm4(bl, rb + (uint32_t)(((chb+4) ^ (oc&7)) << 4));
                #pragma unroll
                for (int mf = 0; mf < MF; mf++) {
                    mma16816(acc[mf][2*nf2  ], ah[mf], bh+0);
                    mma16816(acc[mf][2*nf2  ], ah[mf], bl+0);
                    mma16816(acc[mf][2*nf2  ], al[mf], bh+0);
                    mma16816(acc[mf][2*nf2+1], ah[mf], bh+2);
                    mma16816(acc[mf][2*nf2+1], ah[mf], bl+2);
                    mma16816(acc[mf][2*nf2+1], al[mf], bh+2);
                }
            }
        }
    };

    load_a(0); load_b(0);
    sts_ab(Ab0, Bb0);
    __syncthreads();

    for (int kc = 0; kc < NCH; kc++) {
        if (kc + 1 < NCH) { load_a(kc+1); load_b(kc+1); }
        compute((kc & 1) ? Ab1 : Ab0, (kc & 1) ? Bb1 : Bb0);
        if (kc + 1 < NCH) {
            sts_ab(((kc+1) & 1) ? Ab1 : Ab0, ((kc+1) & 1) ? Bb1 : Bb0);
            __syncthreads();
        }
    }

    // ---- epilogue ----
    const int lrow = lane >> 2, lcol = (lane & 3) * 2;
    #pragma unroll
    for (int mf = 0; mf < MF; mf++) {
        #pragma unroll
        for (int nf = 0; nf < NF; nf++) {
            const int oc = wn*NT + nf*8 + lcol;
            float bx = 0.f, by = 0.f;
            if (bias != nullptr) { bx = __ldg(bias + oc); by = __ldg(bias + oc + 1); }
            #pragma unroll
            for (int rp = 0; rp < 2; rp++) {
                const int m = wm*MT + mf*16 + lrow + rp*8;
                const int y = yb + (m >> 5), x = xb + (m & 31);
                float c0 = acc[mf][nf][rp*2] + bx;
                float c1 = acc[mf][nf][rp*2+1] + by;
                if (RELU) { c0 = fmaxf(c0, 0.f); c1 = fmaxf(c1, 0.f); }
                if (MODE == 0) {
                    *(float2*)(out + ((size_t)b*HW + (size_t)y*Ww + x)*OUT_CS + oc)
                        = make_float2(c0, c1);
                } else {
                    const size_t p = (size_t)y*Ww + x;
                    out[((size_t)b*N + oc  )*HW + p] = c0;
                    out[((size_t)b*N + oc+1)*HW + p] = c1;
                }
            }
        }
    }
}

// ---------------- NCHW -> NHWC tiled transpose ----------------
__global__ void to_nhwc(const float* __restrict__ src, float* __restrict__ dst,
                        int C, int OCS, int cofs)
{
    __shared__ float tl[32][33];
    const int p0 = blockIdx.x*32, c0 = blockIdx.y*32, b = blockIdx.z;
    const int lx = threadIdx.x & 31, ly = threadIdx.x >> 5;
    #pragma unroll
    for (int i = 0; i < 32; i += 8)
        tl[ly+i][lx] = src[((size_t)b*C + c0 + ly + i)*HW + p0 + lx];
    __syncthreads();
    #pragma unroll
    for (int i = 0; i < 32; i += 8)
        dst[((size_t)b*HW + p0 + ly + i)*OCS + cofs + c0 + lx] = tl[lx][ly+i];
}

// ---------------- weight reformat: split fp16 hi/lo + pre-swizzle smem image ----------------
__global__ void reformat_w_split(const float* __restrict__ w, __half* __restrict__ BT,
                                 int COUT, int NPAD, int CIN, int TOT)
{
    int i = blockIdx.x*blockDim.x + threadIdx.x;
    if (i >= TOT) return;
    int j  = i & 31;
    int oc = (i >> 5) % NPAD;
    int kc = i / (32 * NPAD);
    int kidx = kc*32 + j;
    int tap = kidx / CIN, cin = kidx % CIN;
    float v = (oc < COUT) ? w[((size_t)oc*CIN + cin)*9 + tap] : 0.f;
    __half h = __float2half_rn(v);
    __half l = __float2half_rn(v - __half2float(h));
    int sw = oc & 7;
    size_t rowb = ((size_t)kc*NPAD + oc) * 64;
    int ch = j >> 3, pos = j & 7;
    BT[rowb + (size_t)(((ch    ) ^ sw) << 3) + pos] = h;
    BT[rowb + (size_t)(((ch + 4) ^ sw) << 3) + pos] = l;
}

// ---------------- launch ----------------
extern "C" void kernel_launch(void* const* d_in, const int* in_sizes, int n_in,
                              void* d_out, int out_size)
{
    (void)in_sizes; (void)n_in; (void)out_size;
    const float* lr = (const float*)d_in[0];
    const float* hr = (const float*)d_in[1];
    const float* w1 = (const float*)d_in[2];
    const float* b1 = (const float*)d_in[3];
    const float* w2 = (const float*)d_in[4];
    const float* b2 = (const float*)d_in[5];
    const float* wo = (const float*)d_in[6];
    const float* wd = (const float*)d_in[7];
    float* out = (float*)d_out;

    float *plrT, *phrT, *ph1, *ph2, *poff;
    __half *pBT1, *pBT2, *pBTo, *pBTd;
    cudaGetSymbolAddress((void**)&plrT, g_lrT);
    cudaGetSymbolAddress((void**)&phrT, g_hrT);
    cudaGetSymbolAddress((void**)&ph1,  g_h1);
    cudaGetSymbolAddress((void**)&ph2,  g_h2);
    cudaGetSymbolAddress((void**)&poff, g_off);
    cudaGetSymbolAddress((void**)&pBT1, g_BT1);
    cudaGetSymbolAddress((void**)&pBT2, g_BT2);
    cudaGetSymbolAddress((void**)&pBTo, g_BTo);
    cudaGetSymbolAddress((void**)&pBTd, g_BTd);

    const int SZ128 = 2*16384 + 2*128*128;   // 65536
    const int SZ32  = 2*16384 + 2*32*128;    // 40960
    const int SZ64  = 2*16384 + 2*64*128;    // 49152
    cudaFuncSetAttribute(mma_conv<128,2,0,true ,36,4>,
                         cudaFuncAttributeMaxDynamicSharedMemorySize, SZ128);
    cudaFuncSetAttribute(mma_conv<32 ,1,0,false,36,4>,
                         cudaFuncAttributeMaxDynamicSharedMemorySize, SZ32);
    cudaFuncSetAttribute(mma_conv<64 ,2,2,false,18,2>,
                         cudaFuncAttributeMaxDynamicSharedMemorySize, SZ64);

    // launches 0-4 (so conv1 is launch index 5 -> profiled by ncu -s 5 -c 1)
    to_nhwc<<<dim3(800,2,Bn), 256>>>(lr, plrT, 64, 64, 0);
    to_nhwc<<<dim3(800,2,Bn), 256>>>(hr, phrT, 64, 64, 0);
    reformat_w_split<<<(36*128*32+255)/256, 256>>>(w1, pBT1, 128, 128, 128, 36*128*32);
    reformat_w_split<<<(36*128*32+255)/256, 256>>>(w2, pBT2, 128, 128, 128, 36*128*32);
    reformat_w_split<<<(36*32*32 +255)/256, 256>>>(wo, pBTo, 18,  32,  128, 36*32*32);

    // conv1: concat(lrT|hrT)(128) -> 128, relu   [launch 5: PROFILED]
    mma_conv<128,2,0,true ,36,4><<<dim3(5,40,Bn), 256, SZ128>>>(
        plrT, phrT, nullptr, pBT1, b1, ph1, 64, 64, 64, 128);

    reformat_w_split<<<(18*64*32 +255)/256, 256>>>(wd, pBTd, 64,  64,  64,  18*64*32);

    // conv2: 128 -> 128, relu
    mma_conv<128,2,0,true ,36,4><<<dim3(5,40,Bn), 256, SZ128>>>(
        ph1, ph1, nullptr, pBT2, b2, ph2, 128, 128, 128, 128);
    // offset conv: 128 -> 18 (pad 32)
    mma_conv<32 ,1,0,false,36,4><<<dim3(5,40,Bn), 256, SZ32 >>>(
        ph2, ph2, nullptr, pBTo, nullptr, poff, 128, 128, 128, 32);
    // fused deformable sampling + contraction: K=576 -> 64, NCHW out
    mma_conv<64 ,2,2,false,18,2><<<dim3(5,40,Bn), 256, SZ64 >>>(
        phrT, nullptr, poff, pBTd, nullptr, out, 64, 64, 64, 0);
}